// round 5
// baseline (speedup 1.0000x reference)
#include <cuda_runtime.h>
#include <math.h>

// Real spherical harmonics Y_{l,m}, l_max = 8, output [N, 81] fp32.
// Persistent store-bound kernel. Each WARP independently loops over a
// strided chain of 32-point tiles: compute into its smem span (output
// order, stride 81 coprime with 32 banks -> conflict-free STS), syncwarp,
// flush with coalesced streaming float4 stores. No block barriers, no
// wave transitions (grid == resident CTA count).

namespace {
constexpr int LMAX  = 8;
constexpr int NCOLS = (LMAX + 1) * (LMAX + 1);  // 81
constexpr int BLK   = 128;
constexpr int WARPS = BLK / 32;                 // 4
constexpr int WPTS  = 32;                       // points per warp-tile
constexpr int WSPAN = WPTS * NCOLS;             // 2592 floats
constexpr int WQ    = WSPAN / 4;                // 648 float4
constexpr int GRID  = 148 * 5;                  // 740 resident CTAs (smem-bound)

struct KTab { float v[LMAX + 1][LMAX + 1]; };

constexpr double cfact(int n) {
    double r = 1.0;
    for (int i = 2; i <= n; ++i) r *= (double)i;
    return r;
}
constexpr double csqrtd(double x) {
    double g = (x > 1.0) ? x : 1.0;
    for (int i = 0; i < 64; ++i) g = 0.5 * (g + x / g);
    return g;
}
constexpr double CPI = 3.14159265358979323846264338327950288;

constexpr KTab makeK() {
    KTab t{};
    for (int l = 0; l <= LMAX; ++l) {
        for (int m = 0; m <= l; ++m) {
            double k = csqrtd(((2.0 * l + 1.0) / (4.0 * CPI)) *
                              (cfact(l - m) / cfact(l + m)));
            if (m > 0) k *= csqrtd(2.0);
            t.v[l][m] = (float)k;
        }
    }
    return t;
}
}  // namespace

__constant__ KTab KT = makeK();

__global__ void __launch_bounds__(BLK)
sh_kernel(const float* __restrict__ ct_in,
          const float* __restrict__ ph_in,
          float* __restrict__ out, int n)
{
    __shared__ __align__(16) float s[BLK * NCOLS];  // 41472 B

    const int t    = threadIdx.x;
    const int w    = t >> 5;
    const int lane = t & 31;

    float* row = s + t * NCOLS;                 // this thread's 81-slot span
    const float* ws = s + w * WSPAN;            // this warp's 2592-float span

    const int nwarps   = GRID * WARPS;          // total warps in grid
    const int gwarp    = blockIdx.x * WARPS + w;
    const int ntiles   = (n + WPTS - 1) / WPTS; // 62500 for n = 2M

    for (int tile = gwarp; tile < ntiles; tile += nwarps) {
        const int pbase = tile * WPTS;          // first point of this tile
        const int i     = pbase + lane;

        float ct = 0.0f, ph = 0.0f;
        if (i < n) { ct = ct_in[i]; ph = ph_in[i]; }

        float st = sqrtf(fmaxf(1.0f - ct * ct, 0.0f));
        float sp, cp;
        __sincosf(ph, &sp, &cp);

        float cm  = 1.0f;  // cos(m*phi)
        float smv = 0.0f;  // sin(m*phi)
        float pmm = 1.0f;  // P(m,m)

#pragma unroll
        for (int m = 0; m <= LMAX; ++m) {
            if (m > 0) {
                float c2 = cm * cp - smv * sp;
                float s2 = smv * cp + cm * sp;
                cm = c2; smv = s2;
                pmm *= st * (float)(2 * m - 1);   // P(m,m)
            }

            float Pa = pmm;  // l = m
            {
                const float k = KT.v[m][m];
                const int c0 = m * m + m;
                if (m == 0) {
                    row[c0] = k * Pa;
                } else {
                    float kp = k * Pa;
                    row[c0 + m] = kp * cm;
                    row[c0 - m] = kp * smv;
                }
            }

            if (m < LMAX) {
                float Pb = ct * (float)(2 * m + 1) * Pa;  // l = m+1
                {
                    const int l  = m + 1;
                    const float k = KT.v[l][m];
                    const int c0 = l * l + l;
                    if (m == 0) {
                        row[c0] = k * Pb;
                    } else {
                        float kp = k * Pb;
                        row[c0 + m] = kp * cm;
                        row[c0 - m] = kp * smv;
                    }
                }
#pragma unroll
                for (int l = m + 2; l <= LMAX; ++l) {
                    float Pc = ((float)(2 * l - 1) * ct * Pb -
                                (float)(l + m - 1) * Pa) * (1.0f / (float)(l - m));
                    const float k = KT.v[l][m];
                    const int c0 = l * l + l;
                    if (m == 0) {
                        row[c0] = k * Pc;
                    } else {
                        float kp = k * Pc;
                        row[c0 + m] = kp * cm;
                        row[c0 - m] = kp * smv;
                    }
                    Pa = Pb; Pb = Pc;
                }
            }
        }

        __syncwarp();

        // Flush this warp's span: contiguous in smem and gmem.
        int npts = n - pbase;
        if (npts > WPTS) npts = WPTS;
        float* dst = out + (size_t)pbase * NCOLS;

        if (npts == WPTS) {
            const float4* s4 = reinterpret_cast<const float4*>(ws);
            float4* d4 = reinterpret_cast<float4*>(dst);
#pragma unroll 5
            for (int q = lane; q < WQ; q += 32) {
                __stcs(d4 + q, s4[q]);
            }
        } else if (npts > 0) {
            int total = npts * NCOLS;
            for (int f = lane; f < total; f += 32) {
                __stcs(dst + f, ws[f]);
            }
        }

        __syncwarp();   // span consumed before next iteration overwrites it
    }
}

extern "C" void kernel_launch(void* const* d_in, const int* in_sizes, int n_in,
                              void* d_out, int out_size)
{
    int ia = (n_in >= 3) ? 1 : 0;
    const float* ct = (const float*)d_in[ia];
    const float* ph = (const float*)d_in[ia + 1];

    int n = out_size / NCOLS;
    if (n <= 0) return;

    int ntiles = (n + WPTS - 1) / WPTS;
    int maxBlocks = (ntiles + WARPS - 1) / WARPS;   // don't launch idle blocks
    int grid = GRID < maxBlocks ? GRID : maxBlocks;

    sh_kernel<<<grid, BLK>>>(ct, ph, (float*)d_out, n);
}

// round 6
// speedup vs baseline: 1.0613x; 1.0613x over previous
#include <cuda_runtime.h>
#include <math.h>

// Real spherical harmonics Y_{l,m}, l_max = 8, output [N, 81] fp32.
// Store-bound. Per-thread compute into smem in OUTPUT order (stride 81 is
// coprime with 32 banks -> conflict-free STS). Warp-local staging + flush
// (no block barrier). BLK=64: 20.7KB smem/CTA -> ~11 CTAs/SM residency and
// fine-grained CTA backfill, keeping the store pipe continuously fed.

namespace {
constexpr int LMAX  = 8;
constexpr int NCOLS = (LMAX + 1) * (LMAX + 1);  // 81
constexpr int BLK   = 64;
constexpr int WPTS  = 32;                        // points per warp
constexpr int WSPAN = WPTS * NCOLS;              // 2592 floats
constexpr int WQ    = WSPAN / 4;                 // 648 float4

struct KTab { float v[LMAX + 1][LMAX + 1]; };

constexpr double cfact(int n) {
    double r = 1.0;
    for (int i = 2; i <= n; ++i) r *= (double)i;
    return r;
}
constexpr double csqrtd(double x) {
    double g = (x > 1.0) ? x : 1.0;
    for (int i = 0; i < 64; ++i) g = 0.5 * (g + x / g);
    return g;
}
constexpr double CPI = 3.14159265358979323846264338327950288;

constexpr KTab makeK() {
    KTab t{};
    for (int l = 0; l <= LMAX; ++l) {
        for (int m = 0; m <= l; ++m) {
            double k = csqrtd(((2.0 * l + 1.0) / (4.0 * CPI)) *
                              (cfact(l - m) / cfact(l + m)));
            if (m > 0) k *= csqrtd(2.0);
            t.v[l][m] = (float)k;
        }
    }
    return t;
}
}  // namespace

__constant__ KTab KT = makeK();

__global__ void __launch_bounds__(BLK)
sh_kernel(const float* __restrict__ ct_in,
          const float* __restrict__ ph_in,
          float* __restrict__ out, int n)
{
    __shared__ __align__(16) float s[BLK * NCOLS];  // 20736 B, output order

    const int t    = threadIdx.x;
    const int w    = t >> 5;          // warp id in block (0..1)
    const int lane = t & 31;
    const int base = blockIdx.x * BLK;
    const int i    = base + t;

    float ct = 0.0f, ph = 0.0f;
    if (i < n) { ct = __ldcs(ct_in + i); ph = __ldcs(ph_in + i); }

    float st = sqrtf(fmaxf(1.0f - ct * ct, 0.0f));
    float sp, cp;
    __sincosf(ph, &sp, &cp);

    float* row = s + t * NCOLS;

    float cm  = 1.0f;  // cos(m*phi)
    float smv = 0.0f;  // sin(m*phi)
    float pmm = 1.0f;  // P(m,m)

#pragma unroll
    for (int m = 0; m <= LMAX; ++m) {
        if (m > 0) {
            float c2 = cm * cp - smv * sp;
            float s2 = smv * cp + cm * sp;
            cm = c2; smv = s2;
            pmm *= st * (float)(2 * m - 1);   // P(m,m)
        }

        float Pa = pmm;  // l = m
        {
            const float k = KT.v[m][m];
            const int c0 = m * m + m;
            if (m == 0) {
                row[c0] = k * Pa;
            } else {
                float kp = k * Pa;
                row[c0 + m] = kp * cm;
                row[c0 - m] = kp * smv;
            }
        }

        if (m < LMAX) {
            float Pb = ct * (float)(2 * m + 1) * Pa;  // l = m+1
            {
                const int l  = m + 1;
                const float k = KT.v[l][m];
                const int c0 = l * l + l;
                if (m == 0) {
                    row[c0] = k * Pb;
                } else {
                    float kp = k * Pb;
                    row[c0 + m] = kp * cm;
                    row[c0 - m] = kp * smv;
                }
            }
#pragma unroll
            for (int l = m + 2; l <= LMAX; ++l) {
                float Pc = ((float)(2 * l - 1) * ct * Pb -
                            (float)(l + m - 1) * Pa) * (1.0f / (float)(l - m));
                const float k = KT.v[l][m];
                const int c0 = l * l + l;
                if (m == 0) {
                    row[c0] = k * Pc;
                } else {
                    float kp = k * Pc;
                    row[c0 + m] = kp * cm;
                    row[c0 - m] = kp * smv;
                }
                Pa = Pb; Pb = Pc;
            }
        }
    }

    __syncwarp();

    // Per-warp flush: this warp's span is contiguous in smem and gmem.
    const int wbase = base + w * WPTS;        // first point of this warp
    int npts = n - wbase;
    if (npts > WPTS) npts = WPTS;

    float* dst = out + (size_t)wbase * NCOLS;
    const float* ws = s + (size_t)w * WSPAN;

    if (npts == WPTS) {
        const float4* s4 = reinterpret_cast<const float4*>(ws);
        float4* d4 = reinterpret_cast<float4*>(dst);
#pragma unroll 5
        for (int q = lane; q < WQ; q += 32) {
            __stcs(d4 + q, s4[q]);
        }
    } else if (npts > 0) {
        int total = npts * NCOLS;
        for (int f = lane; f < total; f += 32) {
            __stcs(dst + f, ws[f]);
        }
    }
}

extern "C" void kernel_launch(void* const* d_in, const int* in_sizes, int n_in,
                              void* d_out, int out_size)
{
    int ia = (n_in >= 3) ? 1 : 0;
    const float* ct = (const float*)d_in[ia];
    const float* ph = (const float*)d_in[ia + 1];

    int n = out_size / NCOLS;
    if (n <= 0) return;

    int grid = (n + BLK - 1) / BLK;
    sh_kernel<<<grid, BLK>>>(ct, ph, (float*)d_out, n);
}